// round 2
// baseline (speedup 1.0000x reference)
#include <cuda_runtime.h>
#include <cstddef>

#define NS 128
#define DD 128
#define NB 16
#define NT 4096
#define LOG2PI 1.8378770664093453f
#define LOG128 4.852030263919617f

// ---------------- scratch (static device globals; no allocation) ----------------
__device__ float g_A[NS * NS];       // A'[i*128+j] = softmax(transition, axis=1)
__device__ float g_pi[NS];           // softmax(priors)
__device__ float g_U[DD * NS];       // transposed [d][n]: coeff of x   = mean*inv_var
__device__ float g_V[DD * NS];       // transposed [d][n]: coeff of x^2 = -0.5*inv_var
__device__ float g_c2[NS];           // per-state constant
__device__ float g_w[(size_t)NB * NT * NS];   // w[b][t][n] = exp(e - emax)*128/Z
__device__ float g_o[NB * NT];       // o[b][t] = emax + log(Z/128)
__device__ float g_So[NB];           // sum_t o[b][t]
__device__ float g_res[NB];          // per-batch log-likelihood

// ---------------- kernel A: parameter prep ----------------
__global__ void prep_kernel(const float* __restrict__ trans,
                            const float* __restrict__ priors,
                            const float* __restrict__ means,
                            const float* __restrict__ scales) {
    int n = threadIdx.x;  // 128 threads

    // row softmax of transition
    float m = -1e30f;
    for (int k = 0; k < NS; k++) m = fmaxf(m, trans[n * NS + k]);
    float s = 0.f;
    for (int k = 0; k < NS; k++) s += expf(trans[n * NS + k] - m);
    float inv_s = 1.f / s;
    for (int k = 0; k < NS; k++) g_A[n * NS + k] = expf(trans[n * NS + k] - m) * inv_s;

    // softmax of priors (each thread computes redundantly; tiny)
    float pm = -1e30f;
    for (int k = 0; k < NS; k++) pm = fmaxf(pm, priors[k]);
    float ps = 0.f;
    for (int k = 0; k < NS; k++) ps += expf(priors[k] - pm);
    g_pi[n] = expf(priors[n] - pm) / ps;

    // emission params
    float acc = 0.f;
    for (int d = 0; d < DD; d++) {
        float sr = scales[n * DD + d];
        float var = (sr > 20.f) ? sr : log1pf(expf(sr));  // softplus
        var += 1e-6f;
        float inv = 1.f / var;
        float mu = means[n * DD + d];
        g_U[d * NS + n] = mu * inv;
        g_V[d * NS + n] = -0.5f * inv;
        acc += mu * mu * inv + logf(var);
    }
    g_c2[n] = -0.5f * (acc + (float)DD * LOG2PI);
}

// ---------------- kernel B: emission GEMM + fused softmax-normalize ----------------
// grid: 2048 CTAs (16 b * 128 t-tiles of 32), 256 threads; tile 32 rows x 128 states.
__global__ __launch_bounds__(256) void emis_kernel(const float* __restrict__ X) {
    __shared__ float xt[32 * 36];   // x transposed [d][r], padded row stride 36
    __shared__ float qt[32 * 36];   // x^2 transposed
    __shared__ float us[32 * 128];  // U tile [dd][n]
    __shared__ float vs[32 * 128];  // V tile [dd][n]

    int b  = blockIdx.x >> 7;
    int t0 = (blockIdx.x & 127) << 5;
    int tid = threadIdx.x;
    int tx = tid & 31;   // state group: cols 4*tx .. 4*tx+3
    int ty = tid >> 5;   // row group:   rows 4*ty .. 4*ty+3  (one warp per ty)

    float acc[4][4];
#pragma unroll
    for (int r = 0; r < 4; r++)
#pragma unroll
        for (int c = 0; c < 4; c++) acc[r][c] = 0.f;

    const float* Xbase = X + ((size_t)(b * NT + t0)) * DD;

    for (int kb = 0; kb < 4; kb++) {
        int d0 = kb * 32;
        // load X tile (32 rows x 32 d), transpose + square into shared
        {
            int r = tid >> 3;
            int dd0 = (tid & 7) << 2;
            float4 xv = *(const float4*)(Xbase + (size_t)r * DD + d0 + dd0);
            xt[(dd0 + 0) * 36 + r] = xv.x;  qt[(dd0 + 0) * 36 + r] = xv.x * xv.x;
            xt[(dd0 + 1) * 36 + r] = xv.y;  qt[(dd0 + 1) * 36 + r] = xv.y * xv.y;
            xt[(dd0 + 2) * 36 + r] = xv.z;  qt[(dd0 + 2) * 36 + r] = xv.z * xv.z;
            xt[(dd0 + 3) * 36 + r] = xv.w;  qt[(dd0 + 3) * 36 + r] = xv.w * xv.w;
        }
        // load U/V tiles: flat 4096-float copies
        {
            const float4* Us = (const float4*)(g_U + d0 * NS);
            const float4* Vs = (const float4*)(g_V + d0 * NS);
            float4* ud = (float4*)us;
            float4* vd = (float4*)vs;
            for (int i = tid; i < 1024; i += 256) { ud[i] = Us[i]; vd[i] = Vs[i]; }
        }
        __syncthreads();

#pragma unroll
        for (int dd = 0; dd < 32; dd++) {
            float4 xv = *(const float4*)&xt[dd * 36 + 4 * ty];
            float4 qv = *(const float4*)&qt[dd * 36 + 4 * ty];
            float4 uv = *(const float4*)&us[dd * 128 + 4 * tx];
            float4 vv = *(const float4*)&vs[dd * 128 + 4 * tx];
            float xa[4] = {xv.x, xv.y, xv.z, xv.w};
            float qa[4] = {qv.x, qv.y, qv.z, qv.w};
            float ua[4] = {uv.x, uv.y, uv.z, uv.w};
            float va[4] = {vv.x, vv.y, vv.z, vv.w};
#pragma unroll
            for (int r = 0; r < 4; r++)
#pragma unroll
                for (int c = 0; c < 4; c++)
                    acc[r][c] = fmaf(xa[r], ua[c], fmaf(qa[r], va[c], acc[r][c]));
        }
        __syncthreads();
    }

    // epilogue: add c2, row-wise max / Z / w, write w and o
    float4 c2 = *(const float4*)(g_c2 + 4 * tx);
    float c2a[4] = {c2.x, c2.y, c2.z, c2.w};
#pragma unroll
    for (int rr = 0; rr < 4; rr++) {
        float e[4];
#pragma unroll
        for (int c = 0; c < 4; c++) e[c] = acc[rr][c] + c2a[c];
        float m = fmaxf(fmaxf(e[0], e[1]), fmaxf(e[2], e[3]));
#pragma unroll
        for (int off = 16; off; off >>= 1)
            m = fmaxf(m, __shfl_xor_sync(0xffffffffu, m, off));
        float w0 = expf(e[0] - m), w1 = expf(e[1] - m);
        float w2 = expf(e[2] - m), w3 = expf(e[3] - m);
        float z = (w0 + w1) + (w2 + w3);
#pragma unroll
        for (int off = 16; off; off >>= 1)
            z += __shfl_xor_sync(0xffffffffu, z, off);
        float sc = 128.f / z;
        int t = t0 + 4 * ty + rr;
        float4 wout = make_float4(w0 * sc, w1 * sc, w2 * sc, w3 * sc);
        *(float4*)(g_w + ((size_t)(b * NT + t)) * NS + 4 * tx) = wout;
        if (tx == 0) g_o[b * NT + t] = m + logf(z) - LOG128;
    }
}

// ---------------- kernel C: per-batch offset sums ----------------
__global__ void off_kernel() {
    int b = blockIdx.x;
    __shared__ float sh[256];
    float s = 0.f;
    for (int t = threadIdx.x; t < NT; t += 256) s += g_o[b * NT + t];
    sh[threadIdx.x] = s;
    __syncthreads();
    for (int stride = 128; stride; stride >>= 1) {
        if (threadIdx.x < stride) sh[threadIdx.x] += sh[threadIdx.x + stride];
        __syncthreads();
    }
    if (threadIdx.x == 0) g_So[b] = sh[0];
}

// ---------------- kernel D: sequential forward recursion ----------------
// 16 CTAs (one per batch) x 128 threads (one per state j).
__global__ __launch_bounds__(128, 1) void fwd_kernel() {
    int b = blockIdx.x;
    int j = threadIdx.x;
    __shared__ float pbuf[2][NS];

    // A' column j into registers
    float ac[NS];
#pragma unroll
    for (int i = 0; i < NS; i++) ac[i] = g_A[i * NS + j];

    const float* wb = g_w + (size_t)b * NT * NS;

    pbuf[0][j] = g_pi[j] * wb[j];       // P_0 = pi * w_0
    float wv = wb[NS + j];              // w_1
    int cur = 0;
    float plast = pbuf[0][j];

    for (int t = 1; t < NT; t++) {
        int tn = (t + 1 < NT) ? (t + 1) : t;
        float wn = wb[(size_t)tn * NS + j];   // prefetch next w
        __syncthreads();
        const float4* p4 = (const float4*)pbuf[cur];
        float ss[8] = {0.f, 0.f, 0.f, 0.f, 0.f, 0.f, 0.f, 0.f};
#pragma unroll
        for (int q = 0; q < 32; q++) {
            float4 pv = p4[q];
            float& a = ss[q & 7];
            a = fmaf(pv.x, ac[4 * q + 0], a);
            a = fmaf(pv.y, ac[4 * q + 1], a);
            a = fmaf(pv.z, ac[4 * q + 2], a);
            a = fmaf(pv.w, ac[4 * q + 3], a);
        }
        float s = ((ss[0] + ss[1]) + (ss[2] + ss[3])) +
                  ((ss[4] + ss[5]) + (ss[6] + ss[7]));
        float p = s * wv;
        pbuf[cur ^ 1][j] = p;
        plast = p;
        wv = wn;
        cur ^= 1;
    }

    // reduce sum_j P_T
    float v = plast;
#pragma unroll
    for (int off = 16; off; off >>= 1) v += __shfl_xor_sync(0xffffffffu, v, off);
    __shared__ float ws[4];
    __syncthreads();
    if ((j & 31) == 0) ws[j >> 5] = v;
    __syncthreads();
    if (j == 0) g_res[b] = logf(((ws[0] + ws[1]) + (ws[2] + ws[3]))) + g_So[b];
}

// ---------------- kernel E: final sum over batches ----------------
__global__ void fin_kernel(float* out) {
    if (threadIdx.x == 0) {
        float s = 0.f;
        for (int b = 0; b < NB; b++) s += g_res[b];
        out[0] = s;
    }
}

// ---------------- launch ----------------
extern "C" void kernel_launch(void* const* d_in, const int* in_sizes, int n_in,
                              void* d_out, int out_size) {
    const float* X      = (const float*)d_in[0];
    const float* trans  = (const float*)d_in[1];
    const float* priors = (const float*)d_in[2];
    const float* means  = (const float*)d_in[3];
    const float* scales = (const float*)d_in[4];

    prep_kernel<<<1, 128>>>(trans, priors, means, scales);
    emis_kernel<<<2048, 256>>>(X);
    off_kernel<<<NB, 256>>>();
    fwd_kernel<<<NB, 128>>>();
    fin_kernel<<<1, 32>>>((float*)d_out);
}

// round 7
// speedup vs baseline: 1.2982x; 1.2982x over previous
#include <cuda_runtime.h>
#include <cstddef>

#define NS 128
#define DD 128
#define NB 16
#define NT 4096
#define LOG2PI 1.8378770664093453f
#define LOG128 4.852030263919617f

#define FMA2(d, a, b) asm("fma.rn.f32x2 %0, %1, %2, %0;" : "+l"(d) : "l"(a), "l"(b))
#define ADD2(d, a)    asm("add.rn.f32x2 %0, %0, %1;" : "+l"(d) : "l"(a))

// ---------------- scratch (static device globals; no allocation) ----------------
__device__ float g_A[NS * NS];                 // A'[i*128+j] = softmax(transition, axis=1)
__device__ float g_pi[NS];                     // softmax(priors)
__device__ float2 g_UV[DD * NS];               // [d][n]: (mu*inv_var, -0.5*inv_var)
__device__ float g_c2[NS];                     // per-state constant
__device__ float g_w[(size_t)NB * NT * NS];    // w[b][t][n] = exp(e - emax)*128/Z
__device__ float g_o[NB * NT];                 // o[b][t] = emax + log(Z/128)
__device__ float g_So[NB];
__device__ float g_res[NB];

// ---------------- kernel A: parameter prep ----------------
__global__ void prep_kernel(const float* __restrict__ trans,
                            const float* __restrict__ priors,
                            const float* __restrict__ means,
                            const float* __restrict__ scales) {
    int n = threadIdx.x;  // 128 threads

    // row softmax of transition
    float m = -1e30f;
    for (int k = 0; k < NS; k++) m = fmaxf(m, trans[n * NS + k]);
    float s = 0.f;
    for (int k = 0; k < NS; k++) s += expf(trans[n * NS + k] - m);
    float inv_s = 1.f / s;
    for (int k = 0; k < NS; k++) g_A[n * NS + k] = expf(trans[n * NS + k] - m) * inv_s;

    // softmax of priors
    float pm = -1e30f;
    for (int k = 0; k < NS; k++) pm = fmaxf(pm, priors[k]);
    float ps = 0.f;
    for (int k = 0; k < NS; k++) ps += expf(priors[k] - pm);
    g_pi[n] = expf(priors[n] - pm) / ps;

    // emission params
    float acc = 0.f;
    for (int d = 0; d < DD; d++) {
        float sr = scales[n * DD + d];
        float var = (sr > 20.f) ? sr : log1pf(expf(sr));  // softplus
        var += 1e-6f;
        float inv = 1.f / var;
        float mu = means[n * DD + d];
        g_UV[d * NS + n] = make_float2(mu * inv, -0.5f * inv);
        acc += mu * mu * inv + logf(var);
    }
    g_c2[n] = -0.5f * (acc + (float)DD * LOG2PI);
}

// ---------------- kernel B: emission GEMM (packed f32x2) + fused softmax ----------------
// grid: 2048 CTAs (16 b * 128 t-tiles of 32), 256 threads; tile 32 rows x 128 states.
// thread (tx,ty): rows 4*ty..4*ty+3, cols {tx, tx+32, tx+64, tx+96}.
__global__ __launch_bounds__(256) void emis_kernel(const float* __restrict__ X) {
    __shared__ float2 xq[32][38];    // (x, x^2) transposed [dd][r], padded
    __shared__ float2 uvs[32][128];  // (u, v) tile [dd][n]

    int b  = blockIdx.x >> 7;
    int t0 = (blockIdx.x & 127) << 5;
    int tid = threadIdx.x;
    int tx = tid & 31;
    int ty = tid >> 5;

    unsigned long long acc2[16];   // packed (xu, x2v) accumulators, [r][c]
#pragma unroll
    for (int i = 0; i < 16; i++) acc2[i] = 0ull;

    const float* Xbase = X + ((size_t)(b * NT + t0)) * DD;

    for (int kb = 0; kb < 4; kb++) {
        int d0 = kb * 32;
        // load X tile, transpose + square into shared (interleaved x, x^2)
        {
            int r = tid >> 3;
            int dd0 = (tid & 7) << 2;
            float4 xv = *(const float4*)(Xbase + (size_t)r * DD + d0 + dd0);
            xq[dd0 + 0][r] = make_float2(xv.x, xv.x * xv.x);
            xq[dd0 + 1][r] = make_float2(xv.y, xv.y * xv.y);
            xq[dd0 + 2][r] = make_float2(xv.z, xv.z * xv.z);
            xq[dd0 + 3][r] = make_float2(xv.w, xv.w * xv.w);
        }
        // load UV tile: flat float4 copy (32*128 float2 = 2048 float4)
        {
            const float4* src = (const float4*)(g_UV + d0 * NS);
            float4* dst = (float4*)&uvs[0][0];
            for (int i = tid; i < 2048; i += 256) dst[i] = src[i];
        }
        __syncthreads();

#pragma unroll
        for (int dd = 0; dd < 32; dd++) {
            ulonglong2 x01 = *(const ulonglong2*)&xq[dd][4 * ty];
            ulonglong2 x23 = *(const ulonglong2*)&xq[dd][4 * ty + 2];
            unsigned long long px[4] = {x01.x, x01.y, x23.x, x23.y};
            unsigned long long pu[4];
            pu[0] = *(const unsigned long long*)&uvs[dd][tx];
            pu[1] = *(const unsigned long long*)&uvs[dd][tx + 32];
            pu[2] = *(const unsigned long long*)&uvs[dd][tx + 64];
            pu[3] = *(const unsigned long long*)&uvs[dd][tx + 96];
#pragma unroll
            for (int r = 0; r < 4; r++)
#pragma unroll
                for (int c = 0; c < 4; c++)
                    FMA2(acc2[r * 4 + c], px[r], pu[c]);
        }
        __syncthreads();
    }

    // epilogue
    float c2a[4];
    c2a[0] = g_c2[tx];      c2a[1] = g_c2[tx + 32];
    c2a[2] = g_c2[tx + 64]; c2a[3] = g_c2[tx + 96];

#pragma unroll
    for (int rr = 0; rr < 4; rr++) {
        float e[4];
#pragma unroll
        for (int c = 0; c < 4; c++) {
            float lo, hi;
            asm("mov.b64 {%0,%1}, %2;" : "=f"(lo), "=f"(hi) : "l"(acc2[rr * 4 + c]));
            e[c] = lo + hi + c2a[c];
        }
        float m = fmaxf(fmaxf(e[0], e[1]), fmaxf(e[2], e[3]));
#pragma unroll
        for (int off = 16; off; off >>= 1)
            m = fmaxf(m, __shfl_xor_sync(0xffffffffu, m, off));
        float w0 = expf(e[0] - m), w1 = expf(e[1] - m);
        float w2 = expf(e[2] - m), w3 = expf(e[3] - m);
        float z = (w0 + w1) + (w2 + w3);
#pragma unroll
        for (int off = 16; off; off >>= 1)
            z += __shfl_xor_sync(0xffffffffu, z, off);
        float sc = 128.f / z;
        int t = t0 + 4 * ty + rr;
        float* wrow = g_w + ((size_t)(b * NT + t)) * NS;
        wrow[tx]      = w0 * sc;
        wrow[tx + 32] = w1 * sc;
        wrow[tx + 64] = w2 * sc;
        wrow[tx + 96] = w3 * sc;
        if (tx == 0) g_o[b * NT + t] = m + logf(z) - LOG128;
    }
}

// ---------------- kernel C: per-batch offset sums ----------------
__global__ void off_kernel() {
    int b = blockIdx.x;
    __shared__ float sh[8];
    int tid = threadIdx.x;
    float s = 0.f;
    for (int t = tid; t < NT; t += 256) s += g_o[b * NT + t];
#pragma unroll
    for (int off = 16; off; off >>= 1) s += __shfl_xor_sync(0xffffffffu, s, off);
    if ((tid & 31) == 0) sh[tid >> 5] = s;
    __syncthreads();
    if (tid == 0) {
        float tot = 0.f;
#pragma unroll
        for (int k = 0; k < 8; k++) tot += sh[k];
        g_So[b] = tot;
    }
}

// ---------------- kernel D: sequential forward recursion (packed f32x2) ----------------
// 16 CTAs (one per batch) x 128 threads (one per state j).
__global__ __launch_bounds__(128, 1) void fwd_kernel() {
    int b = blockIdx.x;
    int j = threadIdx.x;
    __shared__ alignas(16) float pbuf[2][NS];

    // A' column j, packed in pairs over i: ac2[q] = (A[2q][j], A[2q+1][j])
    unsigned long long ac2[64];
#pragma unroll
    for (int q = 0; q < 64; q++) {
        float a0 = g_A[(2 * q) * NS + j];
        float a1 = g_A[(2 * q + 1) * NS + j];
        asm("mov.b64 %0, {%1,%2};" : "=l"(ac2[q]) : "f"(a0), "f"(a1));
    }

    const float* wb = g_w + (size_t)b * NT * NS;

    pbuf[0][j] = g_pi[j] * wb[j];               // P_0 = pi * w_0
    float wv = wb[NS + j];                      // w_1
    float wn = wb[2 * NS + j];                  // w_2
    int cur = 0;
    float plast = pbuf[0][j];

    for (int t = 1; t < NT; t++) {
        int tp = (t + 2 < NT) ? (t + 2) : (NT - 1);
        float wf = wb[(size_t)tp * NS + j];     // prefetch 2 ahead
        __syncthreads();
        const ulonglong2* p2 = (const ulonglong2*)pbuf[cur];
        unsigned long long ss[8];
#pragma unroll
        for (int k = 0; k < 8; k++) ss[k] = 0ull;
#pragma unroll
        for (int q = 0; q < 32; q++) {
            ulonglong2 pv = p2[q];
            FMA2(ss[(2 * q) & 7], pv.x, ac2[2 * q]);
            FMA2(ss[(2 * q + 1) & 7], pv.y, ac2[2 * q + 1]);
        }
        ADD2(ss[0], ss[4]); ADD2(ss[1], ss[5]);
        ADD2(ss[2], ss[6]); ADD2(ss[3], ss[7]);
        ADD2(ss[0], ss[2]); ADD2(ss[1], ss[3]);
        ADD2(ss[0], ss[1]);
        float lo, hi;
        asm("mov.b64 {%0,%1}, %2;" : "=f"(lo), "=f"(hi) : "l"(ss[0]));
        float p = (lo + hi) * wv;
        pbuf[cur ^ 1][j] = p;
        plast = p;
        wv = wn;
        wn = wf;
        cur ^= 1;
    }

    // reduce sum_j P_T
    float v = plast;
#pragma unroll
    for (int off = 16; off; off >>= 1) v += __shfl_xor_sync(0xffffffffu, v, off);
    __shared__ float ws[4];
    __syncthreads();
    if ((j & 31) == 0) ws[j >> 5] = v;
    __syncthreads();
    if (j == 0) g_res[b] = logf(((ws[0] + ws[1]) + (ws[2] + ws[3]))) + g_So[b];
}

// ---------------- kernel E: final sum over batches ----------------
__global__ void fin_kernel(float* out) {
    if (threadIdx.x == 0) {
        float s = 0.f;
        for (int b = 0; b < NB; b++) s += g_res[b];
        out[0] = s;
    }
}

// ---------------- launch ----------------
extern "C" void kernel_launch(void* const* d_in, const int* in_sizes, int n_in,
                              void* d_out, int out_size) {
    const float* X      = (const float*)d_in[0];
    const float* trans  = (const float*)d_in[1];
    const float* priors = (const float*)d_in[2];
    const float* means  = (const float*)d_in[3];
    const float* scales = (const float*)d_in[4];

    prep_kernel<<<1, 128>>>(trans, priors, means, scales);
    emis_kernel<<<2048, 256>>>(X);
    off_kernel<<<NB, 256>>>();
    fwd_kernel<<<NB, 128>>>();
    fin_kernel<<<1, 32>>>((float*)d_out);
}